// round 10
// baseline (speedup 1.0000x reference)
#include <cuda_runtime.h>
#include <cstdint>

// ---------------------------------------------------------------------------
// Problem constants
// ---------------------------------------------------------------------------
#define BB    32
#define TT    1024
#define CC    512
#define DD    256
#define UU    256
#define OO    256
#define MTOT  (BB*TT)          // 32768

__device__ float g_xin[(size_t)MTOT * DD];
__device__ float g_xz [(size_t)MTOT * 4 * UU];
__device__ float g_hs [(size_t)MTOT * UU];

// 1 noop: keeps LSTM at the ncu capture slot
__global__ void noop_kernel(int* p) { if (p) *p = 0; }

// ---------------------------------------------------------------------------
// Tiled fp32 GEMM (R2 version, proven): C[M,N] = A[M,K] @ W[K,N] + bias[N]
// ---------------------------------------------------------------------------
__global__ __launch_bounds__(256) void gemm_bias_kernel(
    const float* __restrict__ A, const float* __restrict__ W,
    const float* __restrict__ bias, float* __restrict__ C,
    int M, int N, int K)
{
    __shared__ float As[16][128];
    __shared__ float Bs[16][64];

    const int tid = threadIdx.x;
    const int tx  = tid & 15;
    const int ty  = tid >> 4;
    const int m0  = blockIdx.y * 128;
    const int n0  = blockIdx.x * 64;

    const int arow = tid >> 2;
    const int akc  = (tid & 3) * 4;
    const int brow = tid >> 4;
    const int bnc  = (tid & 15) * 4;

    float acc[8][4];
    #pragma unroll
    for (int i = 0; i < 8; i++)
        #pragma unroll
        for (int j = 0; j < 4; j++) acc[i][j] = 0.f;

    for (int kt = 0; kt < K; kt += 16) {
        #pragma unroll
        for (int h = 0; h < 2; h++) {
            int r = arow + h * 64;
            float4 a = *(const float4*)&A[(size_t)(m0 + r) * K + kt + akc];
            As[akc + 0][r] = a.x;
            As[akc + 1][r] = a.y;
            As[akc + 2][r] = a.z;
            As[akc + 3][r] = a.w;
        }
        {
            float4 b = *(const float4*)&W[(size_t)(kt + brow) * N + n0 + bnc];
            *(float4*)&Bs[brow][bnc] = b;
        }
        __syncthreads();

        #pragma unroll
        for (int kk = 0; kk < 16; kk++) {
            float4 b4 = *(const float4*)&Bs[kk][tx * 4];
            float4 a0 = *(const float4*)&As[kk][ty * 8];
            float4 a1 = *(const float4*)&As[kk][ty * 8 + 4];
            float a[8] = {a0.x, a0.y, a0.z, a0.w, a1.x, a1.y, a1.z, a1.w};
            #pragma unroll
            for (int i = 0; i < 8; i++) {
                acc[i][0] += a[i] * b4.x;
                acc[i][1] += a[i] * b4.y;
                acc[i][2] += a[i] * b4.z;
                acc[i][3] += a[i] * b4.w;
            }
        }
        __syncthreads();
    }

    float4 bv = *(const float4*)&bias[n0 + tx * 4];
    #pragma unroll
    for (int i = 0; i < 8; i++) {
        float4 o;
        o.x = acc[i][0] + bv.x;
        o.y = acc[i][1] + bv.y;
        o.z = acc[i][2] + bv.z;
        o.w = acc[i][3] + bv.w;
        *(float4*)&C[(size_t)(m0 + ty * 8 + i) * N + n0 + tx * 4] = o;
    }
}

// ---------------------------------------------------------------------------
// LSTM scan v8 = v7 + h push via st.async.b64 (register path, no TMA/bulk
// engine): 64 gate threads each push a 32B sub-chunk to one peer (4 x b64),
// completing the same pairwise per-source mbarriers. fence.proxy removed.
// ---------------------------------------------------------------------------
#define CLS 8
#define LSTM_THREADS 256

__device__ __forceinline__ float sigm_f(float x) {
    return 1.f / (1.f + __expf(-x));
}
__device__ __forceinline__ float tanh_f(float x) {
    return 2.f / (1.f + __expf(-2.f * x)) - 1.f;
}

#define FMA2(acc, a, b) \
    asm("fma.rn.f32x2 %0, %1, %2, %0;" : "+l"(acc) : "l"(a), "l"(b))

#define MBAR_INIT(addr, cnt) \
    asm volatile("mbarrier.init.shared.b64 [%0], %1;" :: "r"(addr), "r"(cnt) : "memory")

#define MBAR_EXPECT_TX(addr, tx) \
    asm volatile("mbarrier.arrive.expect_tx.shared.b64 _, [%0], %1;" :: "r"(addr), "r"(tx) : "memory")

#define MBAR_WAIT(addr, par) do {                                                  \
    asm volatile("{\n\t.reg .pred P;\n"                                            \
                 "W_%=:\n\t"                                                       \
                 "mbarrier.try_wait.parity.acquire.cluster.shared::cta.b64 "       \
                 "P, [%0], %1, 0x80;\n\t"                                          \
                 "@!P bra W_%=;\n\t}"                                              \
                 :: "r"(addr), "r"(par) : "memory");                               \
} while (0)

#define ST_ASYNC_B64(rd, val, rm)                                                  \
    asm volatile("st.async.shared::cluster.mbarrier::complete_tx::bytes.b64 "      \
                 "[%0], %1, [%2];" :: "r"(rd), "l"(val), "r"(rm) : "memory")

__global__ void __cluster_dims__(CLS, 1, 1) __launch_bounds__(LSTM_THREADS, 1)
lstm_kernel(const float* __restrict__ xz, const float* __restrict__ R,
            float* __restrict__ hs)
{
    __shared__ __align__(16) float h2[2 * 512];         // [buf][k=256][b=2]
    __shared__ __align__(16) float parts[2][16 * 128];  // [buf][w*2+b][c=128]
    __shared__ __align__(16) float hstage[64];          // [u=32][b=2]
    __shared__ __align__(8)  unsigned long long mbar[16]; // [buf][src=8]

    const int tid  = threadIdx.x;
    const int rank = blockIdx.x;
    const int b0   = blockIdx.y * 2;
    const int w    = tid >> 5;
    const int l    = tid & 31;

    // ---- R slice -> registers: thread (w,l) holds k=32w..32w+32, cols 4l..4l+3
    const int gate = l >> 3;
    const int cb   = (4 * l) & 31;
    const int gcol = gate * 256 + rank * 32 + cb;
    ulonglong2 Rreg[32];
    #pragma unroll
    for (int j = 0; j < 32; j++)
        Rreg[j] = *(const ulonglong2*)&R[(size_t)(w * 32 + j) * 1024 + gcol];

    for (int i = tid; i < 1024; i += LSTM_THREADS) h2[i] = 0.f;

    const unsigned mb0 = (unsigned)__cvta_generic_to_shared(&mbar[0]);
    if (tid == 0) {
        #pragma unroll
        for (int i = 0; i < 16; i++) {
            MBAR_INIT(mb0 + i * 8, 1);
            MBAR_EXPECT_TX(mb0 + i * 8, 256);
        }
        asm volatile("fence.mbarrier_init.release.cluster;" ::: "memory");
    }
    __syncthreads();
    asm volatile("barrier.cluster.arrive.aligned;" ::: "memory");
    asm volatile("barrier.cluster.wait.aligned;"   ::: "memory");

    const int gb = tid >> 5;            // gate-thread batch  (tid<64)
    const int gu = tid & 31;            // gate-thread unit
    float creg = 0.f;
    int ph0 = 0, ph1 = 0;

    // ---- hoisted remote push addresses (gate threads: peer p, sub-chunk idx)
    // thread tid<64: p = tid>>3, idx = tid&7. Pushes 32B from hstage[idx*8]
    // to peer p's h2[buf*512 + rank*64 + idx*8], completing peer's mbar[buf][rank].
    unsigned rdl = 0, rml = 0;
    const int pidx = tid & 7;
    if (tid < 64) {
        const int p = tid >> 3;
        const unsigned dl0 = (unsigned)__cvta_generic_to_shared(
            &h2[rank * 64 + pidx * 8]);
        asm volatile("mapa.shared::cluster.u32 %0, %1, %2;"
                     : "=r"(rdl) : "r"(dl0), "r"(p));
        asm volatile("mapa.shared::cluster.u32 %0, %1, %2;"
                     : "=r"(rml) : "r"(mb0 + (unsigned)(rank * 8)), "r"(p));
    }

    // ---- xz prefetch pipeline: load t=0 now; inside step t we load t+1 ----
    const float* xzp = (tid < 64)
        ? &xz[((size_t)(b0 + gb) * TT) * 1024 + rank * 32 + gu] : xz;
    float xzv0 = 0.f, xzv1 = 0.f, xzv2 = 0.f, xzv3 = 0.f;
    if (tid < 64) {
        xzv0 = xzp[0];
        xzv1 = xzp[256];
        xzv2 = xzp[512];
        xzv3 = xzp[768];
    }

    for (int t = 0; t < TT; t++) {
        const int pb = t & 1;

        // prefetch xz for t+1 (consumed NEXT step: full-step distance)
        float nx0 = 0.f, nx1 = 0.f, nx2 = 0.f, nx3 = 0.f;
        if (tid < 64 && t + 1 < TT) {
            const float* p = xzp + (size_t)(t + 1) * 1024;
            nx0 = p[0];
            nx1 = p[256];
            nx2 = p[512];
            nx3 = p[768];
        }

        // wait ONLY for our source slice (rank w -> units 32w..32w+32)
        if (t > 0) {
            const unsigned m = mb0 + (unsigned)((pb * 8 + w) * 8);
            if (pb) { MBAR_WAIT(m, ph1); ph1 ^= 1; }
            else    { MBAR_WAIT(m, ph0); ph0 ^= 1; }
            if (l == 0) MBAR_EXPECT_TX(m, 256);   // re-arm for t+2
        }

        // ---- MMA: z_partial over k in [32w,32w+32), cols 4l..4l+3, b=0,1
        unsigned long long a00 = 0ull, a01 = 0ull, a10 = 0ull, a11 = 0ull;
        const float2* hb = (const float2*)(h2 + pb * 512) + w * 32;
        #pragma unroll
        for (int j = 0; j < 32; j++) {
            float2 hh = hb[j];
            unsigned hx = __float_as_uint(hh.x);
            unsigned hy = __float_as_uint(hh.y);
            unsigned long long hp0, hp1;
            asm("mov.b64 %0, {%1, %1};" : "=l"(hp0) : "r"(hx));
            asm("mov.b64 %0, {%1, %1};" : "=l"(hp1) : "r"(hy));
            FMA2(a00, Rreg[j].x, hp0);
            FMA2(a01, Rreg[j].x, hp1);
            FMA2(a10, Rreg[j].y, hp0);
            FMA2(a11, Rreg[j].y, hp1);
        }
        {
            float* pbuf = parts[pb];
            unsigned p0, p1, p2, p3;
            asm("mov.b64 {%0, %1}, %2;" : "=r"(p0), "=r"(p1) : "l"(a00));
            asm("mov.b64 {%0, %1}, %2;" : "=r"(p2), "=r"(p3) : "l"(a10));
            *(float4*)&pbuf[(w * 2 + 0) * 128 + 4 * l] =
                make_float4(__uint_as_float(p0), __uint_as_float(p1),
                            __uint_as_float(p2), __uint_as_float(p3));
            asm("mov.b64 {%0, %1}, %2;" : "=r"(p0), "=r"(p1) : "l"(a01));
            asm("mov.b64 {%0, %1}, %2;" : "=r"(p2), "=r"(p3) : "l"(a11));
            *(float4*)&pbuf[(w * 2 + 1) * 128 + 4 * l] =
                make_float4(__uint_as_float(p0), __uint_as_float(p1),
                            __uint_as_float(p2), __uint_as_float(p3));
        }

        if (w >= 2) {
            asm volatile("bar.arrive 2, 256;" ::: "memory");
            xzv0 = nx0; xzv1 = nx1; xzv2 = nx2; xzv3 = nx3;
            continue;                      // run ahead into next step
        }
        asm volatile("bar.sync 2, 256;" ::: "memory");

        // ---- gate phase (warps 0,1 == 64 gate threads) ----
        {
            const float* pbuf = parts[pb];
            float z0 = xzv0, z1 = xzv1, z2 = xzv2, z3 = xzv3;
            #pragma unroll
            for (int ww = 0; ww < 8; ww++) {
                const float* p = &pbuf[(ww * 2 + gb) * 128];
                z0 += p[gu];
                z1 += p[32 + gu];
                z2 += p[64 + gu];
                z3 += p[96 + gu];
            }
            float ig = sigm_f(z0);
            float fg = sigm_f(z1);
            float gg = tanh_f(z2);
            float og = sigm_f(z3);
            creg = fg * creg + ig * gg;
            float h = og * tanh_f(creg);

            if (t < TT - 1) {
                hstage[gu * 2 + gb] = h;
                asm volatile("bar.sync 1, 64;" ::: "memory");
                // all 64 gate threads push: thread (p=tid>>3, idx=tid&7)
                // sends 32B (4 x b64) from hstage to peer p. Register path:
                // no bulk engine, no proxy fence.
                {
                    const int nb = pb ^ 1;
                    const unsigned rd = rdl + (unsigned)(nb * 2048);
                    const unsigned rm = rml + (unsigned)(nb * 64);
                    const unsigned long long* s =
                        (const unsigned long long*)&hstage[pidx * 8];
                    unsigned long long d0 = s[0], d1 = s[1], d2 = s[2], d3 = s[3];
                    ST_ASYNC_B64(rd,      d0, rm);
                    ST_ASYNC_B64(rd + 8,  d1, rm);
                    ST_ASYNC_B64(rd + 16, d2, rm);
                    ST_ASYNC_B64(rd + 24, d3, rm);
                }
            }
            // global store off the critical path
            hs[((size_t)(b0 + gb) * TT + t) * UU + rank * 32 + gu] = h;
        }
        xzv0 = nx0; xzv1 = nx1; xzv2 = nx2; xzv3 = nx3;
    }

    asm volatile("barrier.cluster.arrive.aligned;" ::: "memory");
    asm volatile("barrier.cluster.wait.aligned;"   ::: "memory");
}

// ---------------------------------------------------------------------------
// launch
// ---------------------------------------------------------------------------
extern "C" void kernel_launch(void* const* d_in, const int* in_sizes, int n_in,
                              void* d_out, int out_size)
{
    const float* x      = (const float*)d_in[0];
    const float* w_in   = (const float*)d_in[1];
    const float* b_in   = (const float*)d_in[2];
    const float* kernel = (const float*)d_in[3];
    const float* rec_k  = (const float*)d_in[4];
    const float* bias   = (const float*)d_in[5];
    const float* w_out  = (const float*)d_in[6];
    const float* b_out  = (const float*)d_in[7];
    float* out = (float*)d_out;

    float *p_xin, *p_xz, *p_hs;
    cudaGetSymbolAddress((void**)&p_xin, g_xin);
    cudaGetSymbolAddress((void**)&p_xz,  g_xz);
    cudaGetSymbolAddress((void**)&p_hs,  g_hs);

    // 1 noop: LSTM stays at the ncu capture index
    noop_kernel<<<1, 32>>>(nullptr);

    // 1) xin = x @ w_in + b_in          [32768,512]x[512,256]
    gemm_bias_kernel<<<dim3(DD / 64, MTOT / 128), 256>>>(
        x, w_in, b_in, p_xin, MTOT, DD, CC);

    // 2) xz = xin @ kernel + bias       [32768,256]x[256,1024]
    gemm_bias_kernel<<<dim3((4 * UU) / 64, MTOT / 128), 256>>>(
        p_xin, kernel, bias, p_xz, MTOT, 4 * UU, DD);

    // 3) LSTM scan over T=1024
    lstm_kernel<<<dim3(CLS, BB / 2), LSTM_THREADS>>>(p_xz, rec_k, p_hs);

    // 4) out = hs @ w_out + b_out       [32768,256]x[256,256]
    gemm_bias_kernel<<<dim3(OO / 64, MTOT / 128), 256>>>(
        p_hs, w_out, b_out, out, MTOT, OO, UU);
}

// round 13
// speedup vs baseline: 1.0723x; 1.0723x over previous
#include <cuda_runtime.h>
#include <cstdint>

// ---------------------------------------------------------------------------
// Problem constants
// ---------------------------------------------------------------------------
#define BB    32
#define TT    1024
#define CC    512
#define DD    256
#define UU    256
#define OO    256
#define MTOT  (BB*TT)          // 32768

__device__ float g_xin[(size_t)MTOT * DD];
__device__ float g_xz [(size_t)MTOT * 4 * UU];
__device__ float g_hs [(size_t)MTOT * UU];

// 1 noop: keeps LSTM at the ncu capture slot
__global__ void noop_kernel(int* p) { if (p) *p = 0; }

// ---------------------------------------------------------------------------
// GEMM v3: R2 tiling (BM=128,BN=64,BK=16, 256 thr, 8x4) + DOUBLE-BUFFERED
// SMEM with register-staged LDG issued one tile ahead (hides L2/DRAM latency).
// One __syncthreads per iteration: compute reads buf[cur], stores write
// buf[nxt]; buf[cur] is only overwritten 2 iterations later (sync-guarded).
// ---------------------------------------------------------------------------
__global__ __launch_bounds__(256) void gemm_bias_kernel(
    const float* __restrict__ A, const float* __restrict__ W,
    const float* __restrict__ bias, float* __restrict__ C,
    int M, int N, int K)
{
    __shared__ float As[2][16][128];   // [buf][k][m] (transposed A)
    __shared__ float Bs[2][16][64];    // [buf][k][n]

    const int tid = threadIdx.x;
    const int tx  = tid & 15;
    const int ty  = tid >> 4;
    const int m0  = blockIdx.y * 128;
    const int n0  = blockIdx.x * 64;

    const int arow = tid >> 2;           // 0..63
    const int akc  = (tid & 3) * 4;      // 0,4,8,12
    const int brow = tid >> 4;           // 0..15
    const int bnc  = (tid & 15) * 4;     // 0..60

    float acc[8][4];
    #pragma unroll
    for (int i = 0; i < 8; i++)
        #pragma unroll
        for (int j = 0; j < 4; j++) acc[i][j] = 0.f;

    // ---- prologue: load tile 0 into registers, store to buf 0 ----
    float4 ra0 = *(const float4*)&A[(size_t)(m0 + arow) * K + akc];
    float4 ra1 = *(const float4*)&A[(size_t)(m0 + arow + 64) * K + akc];
    float4 rb  = *(const float4*)&W[(size_t)brow * N + n0 + bnc];
    {
        As[0][akc + 0][arow] = ra0.x;
        As[0][akc + 1][arow] = ra0.y;
        As[0][akc + 2][arow] = ra0.z;
        As[0][akc + 3][arow] = ra0.w;
        As[0][akc + 0][arow + 64] = ra1.x;
        As[0][akc + 1][arow + 64] = ra1.y;
        As[0][akc + 2][arow + 64] = ra1.z;
        As[0][akc + 3][arow + 64] = ra1.w;
        *(float4*)&Bs[0][brow][bnc] = rb;
    }
    __syncthreads();

    const int ntiles = K >> 4;
    for (int it = 0; it < ntiles; it++) {
        const int cur = it & 1;
        const int nxt = cur ^ 1;
        const bool more = (it + 1 < ntiles);

        // LDG next tile FIRST (latency overlaps the compute below)
        if (more) {
            const int kt = (it + 1) << 4;
            ra0 = *(const float4*)&A[(size_t)(m0 + arow) * K + kt + akc];
            ra1 = *(const float4*)&A[(size_t)(m0 + arow + 64) * K + kt + akc];
            rb  = *(const float4*)&W[(size_t)(kt + brow) * N + n0 + bnc];
        }

        // compute on buf[cur]
        #pragma unroll
        for (int kk = 0; kk < 16; kk++) {
            float4 b4 = *(const float4*)&Bs[cur][kk][tx * 4];
            float4 a0 = *(const float4*)&As[cur][kk][ty * 8];
            float4 a1 = *(const float4*)&As[cur][kk][ty * 8 + 4];
            float a[8] = {a0.x, a0.y, a0.z, a0.w, a1.x, a1.y, a1.z, a1.w};
            #pragma unroll
            for (int i = 0; i < 8; i++) {
                acc[i][0] += a[i] * b4.x;
                acc[i][1] += a[i] * b4.y;
                acc[i][2] += a[i] * b4.z;
                acc[i][3] += a[i] * b4.w;
            }
        }

        // stage next tile into buf[nxt]
        if (more) {
            As[nxt][akc + 0][arow] = ra0.x;
            As[nxt][akc + 1][arow] = ra0.y;
            As[nxt][akc + 2][arow] = ra0.z;
            As[nxt][akc + 3][arow] = ra0.w;
            As[nxt][akc + 0][arow + 64] = ra1.x;
            As[nxt][akc + 1][arow + 64] = ra1.y;
            As[nxt][akc + 2][arow + 64] = ra1.z;
            As[nxt][akc + 3][arow + 64] = ra1.w;
            *(float4*)&Bs[nxt][brow][bnc] = rb;
        }
        __syncthreads();
    }

    float4 bv = *(const float4*)&bias[n0 + tx * 4];
    #pragma unroll
    for (int i = 0; i < 8; i++) {
        float4 o;
        o.x = acc[i][0] + bv.x;
        o.y = acc[i][1] + bv.y;
        o.z = acc[i][2] + bv.z;
        o.w = acc[i][3] + bv.w;
        *(float4*)&C[(size_t)(m0 + ty * 8 + i) * N + n0 + tx * 4] = o;
    }
}

// ---------------------------------------------------------------------------
// LSTM scan: EXACT R9 version (proven best, 2667us total). Unchanged.
// ---------------------------------------------------------------------------
#define CLS 8
#define LSTM_THREADS 256

__device__ __forceinline__ float sigm_f(float x) {
    return 1.f / (1.f + __expf(-x));
}
__device__ __forceinline__ float tanh_f(float x) {
    return 2.f / (1.f + __expf(-2.f * x)) - 1.f;
}

#define FMA2(acc, a, b) \
    asm("fma.rn.f32x2 %0, %1, %2, %0;" : "+l"(acc) : "l"(a), "l"(b))

#define MBAR_INIT(addr, cnt) \
    asm volatile("mbarrier.init.shared.b64 [%0], %1;" :: "r"(addr), "r"(cnt) : "memory")

#define MBAR_EXPECT_TX(addr, tx) \
    asm volatile("mbarrier.arrive.expect_tx.shared.b64 _, [%0], %1;" :: "r"(addr), "r"(tx) : "memory")

#define MBAR_WAIT(addr, par) do {                                                  \
    asm volatile("{\n\t.reg .pred P;\n"                                            \
                 "W_%=:\n\t"                                                       \
                 "mbarrier.try_wait.parity.acquire.cluster.shared::cta.b64 "       \
                 "P, [%0], %1, 0x80;\n\t"                                          \
                 "@!P bra W_%=;\n\t}"                                              \
                 :: "r"(addr), "r"(par) : "memory");                               \
} while (0)

__global__ void __cluster_dims__(CLS, 1, 1) __launch_bounds__(LSTM_THREADS, 1)
lstm_kernel(const float* __restrict__ xz, const float* __restrict__ R,
            float* __restrict__ hs)
{
    __shared__ __align__(16) float h2[2 * 512];         // [buf][k=256][b=2]
    __shared__ __align__(16) float parts[2][16 * 128];  // [buf][w*2+b][c=128]
    __shared__ __align__(16) float hstage[64];          // [u=32][b=2]
    __shared__ __align__(8)  unsigned long long mbar[16]; // [buf][src=8]

    const int tid  = threadIdx.x;
    const int rank = blockIdx.x;
    const int b0   = blockIdx.y * 2;
    const int w    = tid >> 5;
    const int l    = tid & 31;

    // ---- R slice -> registers: thread (w,l) holds k=32w..32w+32, cols 4l..4l+3
    const int gate = l >> 3;
    const int cb   = (4 * l) & 31;
    const int gcol = gate * 256 + rank * 32 + cb;
    ulonglong2 Rreg[32];
    #pragma unroll
    for (int j = 0; j < 32; j++)
        Rreg[j] = *(const ulonglong2*)&R[(size_t)(w * 32 + j) * 1024 + gcol];

    for (int i = tid; i < 1024; i += LSTM_THREADS) h2[i] = 0.f;

    const unsigned mb0 = (unsigned)__cvta_generic_to_shared(&mbar[0]);
    if (tid == 0) {
        #pragma unroll
        for (int i = 0; i < 16; i++) {
            MBAR_INIT(mb0 + i * 8, 1);
            MBAR_EXPECT_TX(mb0 + i * 8, 256);
        }
        asm volatile("fence.mbarrier_init.release.cluster;" ::: "memory");
    }
    __syncthreads();
    asm volatile("barrier.cluster.arrive.aligned;" ::: "memory");
    asm volatile("barrier.cluster.wait.aligned;"   ::: "memory");

    const int gb = tid >> 5;            // gate-thread batch  (tid<64)
    const int gu = tid & 31;            // gate-thread unit
    float creg = 0.f;
    int ph0 = 0, ph1 = 0;

    const unsigned dst_l[2] = {
        (unsigned)__cvta_generic_to_shared(&h2[0 * 512 + rank * 64]),
        (unsigned)__cvta_generic_to_shared(&h2[1 * 512 + rank * 64])};
    const unsigned src_l =
        (unsigned)__cvta_generic_to_shared(&hstage[0]);

    // hoisted remote addresses for the bulk push (threads 0..7)
    unsigned rdl = 0, rml = 0;
    if (tid < 8) {
        asm volatile("mapa.shared::cluster.u32 %0, %1, %2;"
                     : "=r"(rdl) : "r"(dst_l[0]), "r"(tid));
        asm volatile("mapa.shared::cluster.u32 %0, %1, %2;"
                     : "=r"(rml) : "r"(mb0 + (unsigned)(rank * 8)), "r"(tid));
    }

    // ---- xz prefetch pipeline: load t=0 now; inside step t we load t+1 ----
    const float* xzp = (tid < 64)
        ? &xz[((size_t)(b0 + gb) * TT) * 1024 + rank * 32 + gu] : xz;
    float xzv0 = 0.f, xzv1 = 0.f, xzv2 = 0.f, xzv3 = 0.f;
    if (tid < 64) {
        xzv0 = xzp[0];
        xzv1 = xzp[256];
        xzv2 = xzp[512];
        xzv3 = xzp[768];
    }

    for (int t = 0; t < TT; t++) {
        const int pb = t & 1;

        // prefetch xz for t+1 (consumed in NEXT step's gate phase)
        float nx0 = 0.f, nx1 = 0.f, nx2 = 0.f, nx3 = 0.f;
        if (tid < 64 && t + 1 < TT) {
            const float* p = xzp + (size_t)(t + 1) * 1024;
            nx0 = p[0];
            nx1 = p[256];
            nx2 = p[512];
            nx3 = p[768];
        }

        // wait ONLY for our source slice (rank w -> units 32w..32w+32)
        if (t > 0) {
            const unsigned m = mb0 + (unsigned)((pb * 8 + w) * 8);
            if (pb) { MBAR_WAIT(m, ph1); ph1 ^= 1; }
            else    { MBAR_WAIT(m, ph0); ph0 ^= 1; }
            if (l == 0) MBAR_EXPECT_TX(m, 256);   // re-arm for t+2
        }

        // ---- MMA: z_partial over k in [32w,32w+32), cols 4l..4l+3, b=0,1
        unsigned long long a00 = 0ull, a01 = 0ull, a10 = 0ull, a11 = 0ull;
        const float2* hb = (const float2*)(h2 + pb * 512) + w * 32;
        #pragma unroll
        for (int j = 0; j < 32; j++) {
            float2 hh = hb[j];
            unsigned hx = __float_as_uint(hh.x);
            unsigned hy = __float_as_uint(hh.y);
            unsigned long long hp0, hp1;
            asm("mov.b64 %0, {%1, %1};" : "=l"(hp0) : "r"(hx));
            asm("mov.b64 %0, {%1, %1};" : "=l"(hp1) : "r"(hy));
            FMA2(a00, Rreg[j].x, hp0);
            FMA2(a01, Rreg[j].x, hp1);
            FMA2(a10, Rreg[j].y, hp0);
            FMA2(a11, Rreg[j].y, hp1);
        }
        {
            float* pbuf = parts[pb];
            unsigned p0, p1, p2, p3;
            asm("mov.b64 {%0, %1}, %2;" : "=r"(p0), "=r"(p1) : "l"(a00));
            asm("mov.b64 {%0, %1}, %2;" : "=r"(p2), "=r"(p3) : "l"(a10));
            *(float4*)&pbuf[(w * 2 + 0) * 128 + 4 * l] =
                make_float4(__uint_as_float(p0), __uint_as_float(p1),
                            __uint_as_float(p2), __uint_as_float(p3));
            asm("mov.b64 {%0, %1}, %2;" : "=r"(p0), "=r"(p1) : "l"(a01));
            asm("mov.b64 {%0, %1}, %2;" : "=r"(p2), "=r"(p3) : "l"(a11));
            *(float4*)&pbuf[(w * 2 + 1) * 128 + 4 * l] =
                make_float4(__uint_as_float(p0), __uint_as_float(p1),
                            __uint_as_float(p2), __uint_as_float(p3));
        }

        if (w >= 2) {
            asm volatile("bar.arrive 2, 256;" ::: "memory");
            xzv0 = nx0; xzv1 = nx1; xzv2 = nx2; xzv3 = nx3;
            continue;                      // run ahead into next step
        }
        asm volatile("bar.sync 2, 256;" ::: "memory");

        // ---- gate phase (warps 0,1 == 64 gate threads) ----
        {
            const float* pbuf = parts[pb];
            float z0 = xzv0, z1 = xzv1, z2 = xzv2, z3 = xzv3;
            #pragma unroll
            for (int ww = 0; ww < 8; ww++) {
                const float* p = &pbuf[(ww * 2 + gb) * 128];
                z0 += p[gu];
                z1 += p[32 + gu];
                z2 += p[64 + gu];
                z3 += p[96 + gu];
            }
            float ig = sigm_f(z0);
            float fg = sigm_f(z1);
            float gg = tanh_f(z2);
            float og = sigm_f(z3);
            creg = fg * creg + ig * gg;
            float h = og * tanh_f(creg);

            if (t < TT - 1) {
                hstage[gu * 2 + gb] = h;
                asm volatile("bar.sync 1, 64;" ::: "memory");
                if (tid < 8) {
                    asm volatile("fence.proxy.async.shared::cta;" ::: "memory");
                    const int nb = pb ^ 1;
                    const unsigned rd = rdl + (unsigned)(nb * 2048);
                    const unsigned rm = rml + (unsigned)(nb * 64);
                    asm volatile(
                        "cp.async.bulk.shared::cluster.shared::cta"
                        ".mbarrier::complete_tx::bytes [%0], [%1], 256, [%2];"
                        :: "r"(rd), "r"(src_l), "r"(rm) : "memory");
                }
            }
            // global store off the critical path
            hs[((size_t)(b0 + gb) * TT + t) * UU + rank * 32 + gu] = h;
        }
        xzv0 = nx0; xzv1 = nx1; xzv2 = nx2; xzv3 = nx3;
    }

    asm volatile("barrier.cluster.arrive.aligned;" ::: "memory");
    asm volatile("barrier.cluster.wait.aligned;"   ::: "memory");
}

// ---------------------------------------------------------------------------
// launch
// ---------------------------------------------------------------------------
extern "C" void kernel_launch(void* const* d_in, const int* in_sizes, int n_in,
                              void* d_out, int out_size)
{
    const float* x      = (const float*)d_in[0];
    const float* w_in   = (const float*)d_in[1];
    const float* b_in   = (const float*)d_in[2];
    const float* kernel = (const float*)d_in[3];
    const float* rec_k  = (const float*)d_in[4];
    const float* bias   = (const float*)d_in[5];
    const float* w_out  = (const float*)d_in[6];
    const float* b_out  = (const float*)d_in[7];
    float* out = (float*)d_out;

    float *p_xin, *p_xz, *p_hs;
    cudaGetSymbolAddress((void**)&p_xin, g_xin);
    cudaGetSymbolAddress((void**)&p_xz,  g_xz);
    cudaGetSymbolAddress((void**)&p_hs,  g_hs);

    // 1 noop: LSTM stays at the ncu capture index
    noop_kernel<<<1, 32>>>(nullptr);

    // 1) xin = x @ w_in + b_in          [32768,512]x[512,256]
    gemm_bias_kernel<<<dim3(DD / 64, MTOT / 128), 256>>>(
        x, w_in, b_in, p_xin, MTOT, DD, CC);

    // 2) xz = xin @ kernel + bias       [32768,256]x[256,1024]
    gemm_bias_kernel<<<dim3((4 * UU) / 64, MTOT / 128), 256>>>(
        p_xin, kernel, bias, p_xz, MTOT, 4 * UU, DD);

    // 3) LSTM scan over T=1024
    lstm_kernel<<<dim3(CLS, BB / 2), LSTM_THREADS>>>(p_xz, rec_k, p_hs);

    // 4) out = hs @ w_out + b_out       [32768,256]x[256,256]
    gemm_bias_kernel<<<dim3(OO / 64, MTOT / 128), 256>>>(
        p_hs, w_out, b_out, out, MTOT, OO, UU);
}

// round 14
// speedup vs baseline: 1.0831x; 1.0100x over previous
#include <cuda_runtime.h>
#include <cstdint>

// ---------------------------------------------------------------------------
// Problem constants
// ---------------------------------------------------------------------------
#define BB    32
#define TT    1024
#define CC    512
#define DD    256
#define UU    256
#define OO    256
#define MTOT  (BB*TT)          // 32768

__device__ float g_xin[(size_t)MTOT * DD];
__device__ float g_xz [(size_t)MTOT * 4 * UU];
__device__ float g_hs [(size_t)MTOT * UU];

// 1 noop: keeps LSTM at the ncu capture slot
__global__ void noop_kernel(int* p) { if (p) *p = 0; }

#define FMA2(acc, a, b) \
    asm("fma.rn.f32x2 %0, %1, %2, %0;" : "+l"(acc) : "l"(a), "l"(b))

// ---------------------------------------------------------------------------
// GEMM v4: R13 double-buffered tiling (BM=128,BN=64,BK=16, 256 thr, 8x4)
// + packed fma.rn.f32x2 over M-pairs. As is transposed so LDS.128 of 4
// consecutive m-values IS two packed f32x2 A-operands (zero packing movs);
// only the 4 B-broadcast pairs need mov.b64 (ALU pipe, overlaps FMA).
// Rounding identical to scalar FFMA -> rel_err must be bit-identical.
// ---------------------------------------------------------------------------
__global__ __launch_bounds__(256) void gemm_bias_kernel(
    const float* __restrict__ A, const float* __restrict__ W,
    const float* __restrict__ bias, float* __restrict__ C,
    int M, int N, int K)
{
    __shared__ float As[2][16][128];   // [buf][k][m] (transposed A)
    __shared__ float Bs[2][16][64];    // [buf][k][n]

    const int tid = threadIdx.x;
    const int tx  = tid & 15;
    const int ty  = tid >> 4;
    const int m0  = blockIdx.y * 128;
    const int n0  = blockIdx.x * 64;

    const int arow = tid >> 2;           // 0..63
    const int akc  = (tid & 3) * 4;      // 0,4,8,12
    const int brow = tid >> 4;           // 0..15
    const int bnc  = (tid & 15) * 4;     // 0..60

    // acc2[mp][j] = packed pair {C[2mp][j], C[2mp+1][j]}, mp=0..3, j=0..3
    unsigned long long acc2[4][4];
    #pragma unroll
    for (int i = 0; i < 4; i++)
        #pragma unroll
        for (int j = 0; j < 4; j++) acc2[i][j] = 0ull;

    // ---- prologue: load tile 0 into registers, store to buf 0 ----
    float4 ra0 = *(const float4*)&A[(size_t)(m0 + arow) * K + akc];
    float4 ra1 = *(const float4*)&A[(size_t)(m0 + arow + 64) * K + akc];
    float4 rb  = *(const float4*)&W[(size_t)brow * N + n0 + bnc];
    {
        As[0][akc + 0][arow] = ra0.x;
        As[0][akc + 1][arow] = ra0.y;
        As[0][akc + 2][arow] = ra0.z;
        As[0][akc + 3][arow] = ra0.w;
        As[0][akc + 0][arow + 64] = ra1.x;
        As[0][akc + 1][arow + 64] = ra1.y;
        As[0][akc + 2][arow + 64] = ra1.z;
        As[0][akc + 3][arow + 64] = ra1.w;
        *(float4*)&Bs[0][brow][bnc] = rb;
    }
    __syncthreads();

    const int ntiles = K >> 4;
    for (int it = 0; it < ntiles; it++) {
        const int cur = it & 1;
        const int nxt = cur ^ 1;
        const bool more = (it + 1 < ntiles);

        // LDG next tile FIRST (latency overlaps the compute below)
        if (more) {
            const int kt = (it + 1) << 4;
            ra0 = *(const float4*)&A[(size_t)(m0 + arow) * K + kt + akc];
            ra1 = *(const float4*)&A[(size_t)(m0 + arow + 64) * K + kt + akc];
            rb  = *(const float4*)&W[(size_t)(kt + brow) * N + n0 + bnc];
        }

        // compute on buf[cur] with packed f32x2 FMAs
        #pragma unroll
        for (int kk = 0; kk < 16; kk++) {
            // A m-pairs: LDS.128 == 2 packed pairs each (transposed layout)
            ulonglong2 ap0 = *(const ulonglong2*)&As[cur][kk][ty * 8];
            ulonglong2 ap1 = *(const ulonglong2*)&As[cur][kk][ty * 8 + 4];
            float4 b4 = *(const float4*)&Bs[cur][kk][tx * 4];
            // B broadcast pairs {b,b}
            unsigned long long bb0, bb1, bb2, bb3;
            {
                unsigned u0 = __float_as_uint(b4.x);
                unsigned u1 = __float_as_uint(b4.y);
                unsigned u2 = __float_as_uint(b4.z);
                unsigned u3 = __float_as_uint(b4.w);
                asm("mov.b64 %0, {%1, %1};" : "=l"(bb0) : "r"(u0));
                asm("mov.b64 %0, {%1, %1};" : "=l"(bb1) : "r"(u1));
                asm("mov.b64 %0, {%1, %1};" : "=l"(bb2) : "r"(u2));
                asm("mov.b64 %0, {%1, %1};" : "=l"(bb3) : "r"(u3));
            }
            FMA2(acc2[0][0], ap0.x, bb0);
            FMA2(acc2[0][1], ap0.x, bb1);
            FMA2(acc2[0][2], ap0.x, bb2);
            FMA2(acc2[0][3], ap0.x, bb3);
            FMA2(acc2[1][0], ap0.y, bb0);
            FMA2(acc2[1][1], ap0.y, bb1);
            FMA2(acc2[1][2], ap0.y, bb2);
            FMA2(acc2[1][3], ap0.y, bb3);
            FMA2(acc2[2][0], ap1.x, bb0);
            FMA2(acc2[2][1], ap1.x, bb1);
            FMA2(acc2[2][2], ap1.x, bb2);
            FMA2(acc2[2][3], ap1.x, bb3);
            FMA2(acc2[3][0], ap1.y, bb0);
            FMA2(acc2[3][1], ap1.y, bb1);
            FMA2(acc2[3][2], ap1.y, bb2);
            FMA2(acc2[3][3], ap1.y, bb3);
        }

        // stage next tile into buf[nxt]
        if (more) {
            As[nxt][akc + 0][arow] = ra0.x;
            As[nxt][akc + 1][arow] = ra0.y;
            As[nxt][akc + 2][arow] = ra0.z;
            As[nxt][akc + 3][arow] = ra0.w;
            As[nxt][akc + 0][arow + 64] = ra1.x;
            As[nxt][akc + 1][arow + 64] = ra1.y;
            As[nxt][akc + 2][arow + 64] = ra1.z;
            As[nxt][akc + 3][arow + 64] = ra1.w;
            *(float4*)&Bs[nxt][brow][bnc] = rb;
        }
        __syncthreads();
    }

    // epilogue: unpack pairs, add bias, store (two m-rows per acc2 row)
    float4 bv = *(const float4*)&bias[n0 + tx * 4];
    const float bbv[4] = {bv.x, bv.y, bv.z, bv.w};
    #pragma unroll
    for (int mp = 0; mp < 4; mp++) {
        float lo[4], hi[4];
        #pragma unroll
        for (int j = 0; j < 4; j++) {
            unsigned l_, h_;
            asm("mov.b64 {%0, %1}, %2;" : "=r"(l_), "=r"(h_) : "l"(acc2[mp][j]));
            lo[j] = __uint_as_float(l_) + bbv[j];
            hi[j] = __uint_as_float(h_) + bbv[j];
        }
        float* cp0 = &C[(size_t)(m0 + ty * 8 + 2 * mp) * N + n0 + tx * 4];
        float* cp1 = &C[(size_t)(m0 + ty * 8 + 2 * mp + 1) * N + n0 + tx * 4];
        *(float4*)cp0 = make_float4(lo[0], lo[1], lo[2], lo[3]);
        *(float4*)cp1 = make_float4(hi[0], hi[1], hi[2], hi[3]);
    }
}

// ---------------------------------------------------------------------------
// LSTM scan: EXACT R13/R9 version (proven best). Unchanged.
// ---------------------------------------------------------------------------
#define CLS 8
#define LSTM_THREADS 256

__device__ __forceinline__ float sigm_f(float x) {
    return 1.f / (1.f + __expf(-x));
}
__device__ __forceinline__ float tanh_f(float x) {
    return 2.f / (1.f + __expf(-2.f * x)) - 1.f;
}

#define MBAR_INIT(addr, cnt) \
    asm volatile("mbarrier.init.shared.b64 [%0], %1;" :: "r"(addr), "r"(cnt) : "memory")

#define MBAR_EXPECT_TX(addr, tx) \
    asm volatile("mbarrier.arrive.expect_tx.shared.b64 _, [%0], %1;" :: "r"(addr), "r"(tx) : "memory")

#define MBAR_WAIT(addr, par) do {                                                  \
    asm volatile("{\n\t.reg .pred P;\n"                                            \
                 "W_%=:\n\t"                                                       \
                 "mbarrier.try_wait.parity.acquire.cluster.shared::cta.b64 "       \
                 "P, [%0], %1, 0x80;\n\t"                                          \
                 "@!P bra W_%=;\n\t}"                                              \
                 :: "r"(addr), "r"(par) : "memory");                               \
} while (0)

__global__ void __cluster_dims__(CLS, 1, 1) __launch_bounds__(LSTM_THREADS, 1)
lstm_kernel(const float* __restrict__ xz, const float* __restrict__ R,
            float* __restrict__ hs)
{
    __shared__ __align__(16) float h2[2 * 512];         // [buf][k=256][b=2]
    __shared__ __align__(16) float parts[2][16 * 128];  // [buf][w*2+b][c=128]
    __shared__ __align__(16) float hstage[64];          // [u=32][b=2]
    __shared__ __align__(8)  unsigned long long mbar[16]; // [buf][src=8]

    const int tid  = threadIdx.x;
    const int rank = blockIdx.x;
    const int b0   = blockIdx.y * 2;
    const int w    = tid >> 5;
    const int l    = tid & 31;

    // ---- R slice -> registers: thread (w,l) holds k=32w..32w+32, cols 4l..4l+3
    const int gate = l >> 3;
    const int cb   = (4 * l) & 31;
    const int gcol = gate * 256 + rank * 32 + cb;
    ulonglong2 Rreg[32];
    #pragma unroll
    for (int j = 0; j < 32; j++)
        Rreg[j] = *(const ulonglong2*)&R[(size_t)(w * 32 + j) * 1024 + gcol];

    for (int i = tid; i < 1024; i += LSTM_THREADS) h2[i] = 0.f;

    const unsigned mb0 = (unsigned)__cvta_generic_to_shared(&mbar[0]);
    if (tid == 0) {
        #pragma unroll
        for (int i = 0; i < 16; i++) {
            MBAR_INIT(mb0 + i * 8, 1);
            MBAR_EXPECT_TX(mb0 + i * 8, 256);
        }
        asm volatile("fence.mbarrier_init.release.cluster;" ::: "memory");
    }
    __syncthreads();
    asm volatile("barrier.cluster.arrive.aligned;" ::: "memory");
    asm volatile("barrier.cluster.wait.aligned;"   ::: "memory");

    const int gb = tid >> 5;            // gate-thread batch  (tid<64)
    const int gu = tid & 31;            // gate-thread unit
    float creg = 0.f;
    int ph0 = 0, ph1 = 0;

    const unsigned dst_l[2] = {
        (unsigned)__cvta_generic_to_shared(&h2[0 * 512 + rank * 64]),
        (unsigned)__cvta_generic_to_shared(&h2[1 * 512 + rank * 64])};
    const unsigned src_l =
        (unsigned)__cvta_generic_to_shared(&hstage[0]);

    // hoisted remote addresses for the bulk push (threads 0..7)
    unsigned rdl = 0, rml = 0;
    if (tid < 8) {
        asm volatile("mapa.shared::cluster.u32 %0, %1, %2;"
                     : "=r"(rdl) : "r"(dst_l[0]), "r"(tid));
        asm volatile("mapa.shared::cluster.u32 %0, %1, %2;"
                     : "=r"(rml) : "r"(mb0 + (unsigned)(rank * 8)), "r"(tid));
    }

    // ---- xz prefetch pipeline: load t=0 now; inside step t we load t+1 ----
    const float* xzp = (tid < 64)
        ? &xz[((size_t)(b0 + gb) * TT) * 1024 + rank * 32 + gu] : xz;
    float xzv0 = 0.f, xzv1 = 0.f, xzv2 = 0.f, xzv3 = 0.f;
    if (tid < 64) {
        xzv0 = xzp[0];
        xzv1 = xzp[256];
        xzv2 = xzp[512];
        xzv3 = xzp[768];
    }

    for (int t = 0; t < TT; t++) {
        const int pb = t & 1;

        // prefetch xz for t+1 (consumed in NEXT step's gate phase)
        float nx0 = 0.f, nx1 = 0.f, nx2 = 0.f, nx3 = 0.f;
        if (tid < 64 && t + 1 < TT) {
            const float* p = xzp + (size_t)(t + 1) * 1024;
            nx0 = p[0];
            nx1 = p[256];
            nx2 = p[512];
            nx3 = p[768];
        }

        // wait ONLY for our source slice (rank w -> units 32w..32w+32)
        if (t > 0) {
            const unsigned m = mb0 + (unsigned)((pb * 8 + w) * 8);
            if (pb) { MBAR_WAIT(m, ph1); ph1 ^= 1; }
            else    { MBAR_WAIT(m, ph0); ph0 ^= 1; }
            if (l == 0) MBAR_EXPECT_TX(m, 256);   // re-arm for t+2
        }

        // ---- MMA: z_partial over k in [32w,32w+32), cols 4l..4l+3, b=0,1
        unsigned long long a00 = 0ull, a01 = 0ull, a10 = 0ull, a11 = 0ull;
        const float2* hb = (const float2*)(h2 + pb * 512) + w * 32;
        #pragma unroll
        for (int j = 0; j < 32; j++) {
            float2 hh = hb[j];
            unsigned hx = __float_as_uint(hh.x);
            unsigned hy = __float_as_uint(hh.y);
            unsigned long long hp0, hp1;
            asm("mov.b64 %0, {%1, %1};" : "=l"(hp0) : "r"(hx));
            asm("mov.b64 %0, {%1, %1};" : "=l"(hp1) : "r"(hy));
            FMA2(a00, Rreg[j].x, hp0);
            FMA2(a01, Rreg[j].x, hp1);
            FMA2(a10, Rreg[j].y, hp0);
            FMA2(a11, Rreg[j].y, hp1);
        }
        {
            float* pbuf = parts[pb];
            unsigned p0, p1, p2, p3;
            asm("mov.b64 {%0, %1}, %2;" : "=r"(p0), "=r"(p1) : "l"(a00));
            asm("mov.b64 {%0, %1}, %2;" : "=r"(p2), "=r"(p3) : "l"(a10));
            *(float4*)&pbuf[(w * 2 + 0) * 128 + 4 * l] =
                make_float4(__uint_as_float(p0), __uint_as_float(p1),
                            __uint_as_float(p2), __uint_as_float(p3));
            asm("mov.b64 {%0, %1}, %2;" : "=r"(p0), "=r"(p1) : "l"(a01));
            asm("mov.b64 {%0, %1}, %2;" : "=r"(p2), "=r"(p3) : "l"(a11));
            *(float4*)&pbuf[(w * 2 + 1) * 128 + 4 * l] =
                make_float4(__uint_as_float(p0), __uint_as_float(p1),
                            __uint_as_float(p2), __uint_as_float(p3));
        }

        if (w >= 2) {
            asm volatile("bar.arrive 2, 256;" ::: "memory");
            xzv0 = nx0; xzv1 = nx1; xzv2 = nx2; xzv3 = nx3;
            continue;                      // run ahead into next step
        }
        asm volatile("bar.sync 2, 256;" ::: "memory");

        // ---- gate phase (warps 0,1 == 64 gate threads) ----
        {
            const float* pbuf = parts[pb];
            float z0 = xzv0, z1 = xzv1, z2 = xzv2, z3 = xzv3;
            #pragma unroll
            for (int ww = 0; ww < 8; ww++) {
                const float* p = &pbuf[(ww * 2 + gb) * 128];
                z0 += p[gu];
                z1 += p[32 + gu];
                z2 += p[64 + gu];
                z3 += p[96 + gu];
            }
            float ig = sigm_f(z0);
            float fg = sigm_f(z1);
            float gg = tanh_f(z2);
            float og = sigm_f(z3);
            creg = fg * creg + ig * gg;
            float h = og * tanh_f(creg);

            if (t < TT - 1) {
                hstage[gu * 2 + gb] = h;
                asm volatile("bar.sync 1, 64;" ::: "memory");
                if (tid < 8) {
                    asm volatile("fence.proxy.async.shared::cta;" ::: "memory");
                    const int nb = pb ^ 1;
                    const unsigned rd = rdl + (unsigned)(nb * 2048);
                    const unsigned rm = rml + (unsigned)(nb * 64);
                    asm volatile(
                        "cp.async.bulk.shared::cluster.shared::cta"
                        ".mbarrier::complete_tx::bytes [%0], [%1], 256, [%2];"
                        :: "r"(rd), "r"(src_l), "r"(rm) : "memory");
                }
            }
            // global store off the critical path
            hs[((size_t)(b0 + gb) * TT + t) * UU + rank * 32 + gu] = h;
        }
        xzv0 = nx0; xzv1 = nx1; xzv2 = nx2; xzv3 = nx3;
    }

    asm volatile("barrier.cluster.arrive.aligned;" ::: "memory");
    asm volatile("barrier.cluster.wait.aligned;"   ::: "memory");
}

// ---------------------------------------------------------------------------
// launch
// ---------------------------------------------------------------------------
extern "C" void kernel_launch(void* const* d_in, const int* in_sizes, int n_in,
                              void* d_out, int out_size)
{
    const float* x      = (const float*)d_in[0];
    const float* w_in   = (const float*)d_in[1];
    const float* b_in   = (const float*)d_in[2];
    const float* kernel = (const float*)d_in[3];
    const float* rec_k  = (const float*)d_in[4];
    const float* bias   = (const float*)d_in[5];
    const float* w_out  = (const float*)d_in[6];
    const float* b_out  = (const float*)d_in[7];
    float* out = (float*)d_out;

    float *p_xin, *p_xz, *p_hs;
    cudaGetSymbolAddress((void**)&p_xin, g_xin);
    cudaGetSymbolAddress((void**)&p_xz,  g_xz);
    cudaGetSymbolAddress((void**)&p_hs,  g_hs);

    // 1 noop: LSTM stays at the ncu capture index
    noop_kernel<<<1, 32>>>(nullptr);

    // 1) xin = x @ w_in + b_in          [32768,512]x[512,256]
    gemm_bias_kernel<<<dim3(DD / 64, MTOT / 128), 256>>>(
        x, w_in, b_in, p_xin, MTOT, DD, CC);

    // 2) xz = xin @ kernel + bias       [32768,256]x[256,1024]
    gemm_bias_kernel<<<dim3((4 * UU) / 64, MTOT / 128), 256>>>(
        p_xin, kernel, bias, p_xz, MTOT, 4 * UU, DD);

    // 3) LSTM scan over T=1024
    lstm_kernel<<<dim3(CLS, BB / 2), LSTM_THREADS>>>(p_xz, rec_k, p_hs);

    // 4) out = hs @ w_out + b_out       [32768,256]x[256,256]
    gemm_bias_kernel<<<dim3(OO / 64, MTOT / 128), 256>>>(
        p_hs, w_out, b_out, out, MTOT, OO, UU);
}